// round 5
// baseline (speedup 1.0000x reference)
#include <cuda_runtime.h>
#include <math.h>

#define BB 16
#define LL 512
#define HIDN 768
#define HH 12
#define DD 64
#define NSTRUCT 5
#define BH (BB*HH)   // 192

typedef unsigned long long ull;

// ---- packed f32x2 helpers ----
__device__ __forceinline__ void fma2(ull &d, ull a, ull b) {
    asm("fma.rn.f32x2 %0, %1, %2, %0;" : "+l"(d) : "l"(a), "l"(b));
}
__device__ __forceinline__ void mul2(ull &d, ull s) {
    asm("mul.rn.f32x2 %0, %0, %1;" : "+l"(d) : "l"(s));
}
__device__ __forceinline__ ull pack2(float lo, float hi) {
    ull r; asm("mov.b64 %0, {%1, %2};" : "=l"(r) : "f"(lo), "f"(hi)); return r;
}
__device__ __forceinline__ float2 unpack2(ull v) {
    float2 r; asm("mov.b64 {%0, %1}, %2;" : "=f"(r.x), "=f"(r.y) : "l"(v)); return r;
}

// ---------------- scratch ----------------
__device__ float    g_Q [BH * LL * DD];
__device__ float    g_K [BH * LL * DD];
__device__ float    g_V [BH * LL * DD];
__device__ float    g_QB[NSTRUCT * BH * LL * DD];
__device__ unsigned g_MB[NSTRUCT * BB * LL * (LL/32)];   // packed structure mask

// =============================================================================
// Kernel 0: pack structure mask to bits.
// =============================================================================
__global__ void __launch_bounds__(256) pack_mask(const float* __restrict__ smask)
{
    size_t e = (size_t)blockIdx.x * 256 + threadIdx.x;
    float v = smask[e];
    unsigned bal = __ballot_sync(0xffffffffu, v != 0.f);
    if ((threadIdx.x & 31) == 0) g_MB[e >> 5] = bal;
}

// =============================================================================
// Kernel 1: fused QKV projection. 128x128 tile, BK=16, 256 thr, 8x8 micro.
// =============================================================================
__global__ void __launch_bounds__(256, 2) qkv_kernel(
    const float* __restrict__ hs,
    const float* __restrict__ Wq, const float* __restrict__ bq,
    const float* __restrict__ Wk, const float* __restrict__ bk,
    const float* __restrict__ Wv, const float* __restrict__ bv)
{
    const int z = blockIdx.z;
    const float* W    = (z == 0) ? Wq : (z == 1) ? Wk : Wv;
    const float* bias = (z == 0) ? bq : (z == 1) ? bk : bv;
    float* dst        = (z == 0) ? g_Q : (z == 1) ? g_K : g_V;

    __shared__ __align__(16) float As[16 * 132];
    __shared__ __align__(16) float Bs[16 * 132];

    const int t  = threadIdx.x;
    const int m0 = blockIdx.x * 128;
    const int n0 = blockIdx.y * 128;
    const int r  = t >> 2;
    const int kq = t & 3;
    const int ty = t >> 4;
    const int tx = t & 15;

    float c[8][8];
#pragma unroll
    for (int i = 0; i < 8; i++)
#pragma unroll
        for (int j = 0; j < 8; j++) c[i][j] = 0.f;

    float4 pa0 = *(const float4*)(hs + (size_t)(m0 + r)      * HIDN + kq * 4);
    float4 pa1 = *(const float4*)(hs + (size_t)(m0 + 64 + r) * HIDN + kq * 4);
    float4 pb0 = *(const float4*)(W  + (size_t)(n0 + r)      * HIDN + kq * 4);
    float4 pb1 = *(const float4*)(W  + (size_t)(n0 + 64 + r) * HIDN + kq * 4);

    for (int k0 = 0; k0 < HIDN; k0 += 16) {
        As[(kq*4+0)*132 + r]      = pa0.x;
        As[(kq*4+1)*132 + r]      = pa0.y;
        As[(kq*4+2)*132 + r]      = pa0.z;
        As[(kq*4+3)*132 + r]      = pa0.w;
        As[(kq*4+0)*132 + 64 + r] = pa1.x;
        As[(kq*4+1)*132 + 64 + r] = pa1.y;
        As[(kq*4+2)*132 + 64 + r] = pa1.z;
        As[(kq*4+3)*132 + 64 + r] = pa1.w;
        Bs[(kq*4+0)*132 + r]      = pb0.x;
        Bs[(kq*4+1)*132 + r]      = pb0.y;
        Bs[(kq*4+2)*132 + r]      = pb0.z;
        Bs[(kq*4+3)*132 + r]      = pb0.w;
        Bs[(kq*4+0)*132 + 64 + r] = pb1.x;
        Bs[(kq*4+1)*132 + 64 + r] = pb1.y;
        Bs[(kq*4+2)*132 + 64 + r] = pb1.z;
        Bs[(kq*4+3)*132 + 64 + r] = pb1.w;
        __syncthreads();

        if (k0 + 16 < HIDN) {
            pa0 = *(const float4*)(hs + (size_t)(m0 + r)      * HIDN + k0 + 16 + kq * 4);
            pa1 = *(const float4*)(hs + (size_t)(m0 + 64 + r) * HIDN + k0 + 16 + kq * 4);
            pb0 = *(const float4*)(W  + (size_t)(n0 + r)      * HIDN + k0 + 16 + kq * 4);
            pb1 = *(const float4*)(W  + (size_t)(n0 + 64 + r) * HIDN + k0 + 16 + kq * 4);
        }

#pragma unroll
        for (int k = 0; k < 16; k++) {
            float4 a0 = *(const float4*)&As[k*132 + ty*8];
            float4 a1 = *(const float4*)&As[k*132 + ty*8 + 4];
            float4 b0 = *(const float4*)&Bs[k*132 + tx*4];
            float4 b1 = *(const float4*)&Bs[k*132 + 64 + tx*4];
            float a[8] = {a0.x,a0.y,a0.z,a0.w,a1.x,a1.y,a1.z,a1.w};
            float bb[8] = {b0.x,b0.y,b0.z,b0.w,b1.x,b1.y,b1.z,b1.w};
#pragma unroll
            for (int i = 0; i < 8; i++)
#pragma unroll
                for (int j = 0; j < 8; j++) c[i][j] += a[i] * bb[j];
        }
        __syncthreads();
    }

    const int h0 = n0 >> 6;
    float bj[8];
#pragma unroll
    for (int j = 0; j < 4; ++j) bj[j]     = bias[n0 + tx*4 + j];
#pragma unroll
    for (int j = 0; j < 4; ++j) bj[4 + j] = bias[n0 + 64 + tx*4 + j];

#pragma unroll
    for (int i = 0; i < 8; i++) {
        int m = m0 + ty*8 + i;
        int b = m >> 9, l = m & 511;
        float4 o0, o1;
        o0.x = c[i][0]+bj[0]; o0.y = c[i][1]+bj[1]; o0.z = c[i][2]+bj[2]; o0.w = c[i][3]+bj[3];
        o1.x = c[i][4]+bj[4]; o1.y = c[i][5]+bj[5]; o1.z = c[i][6]+bj[6]; o1.w = c[i][7]+bj[7];
        *(float4*)(dst + ((size_t)(b*HH + h0)     * LL + l) * DD + tx*4) = o0;
        *(float4*)(dst + ((size_t)(b*HH + h0 + 1) * LL + l) * DD + tx*4) = o1;
    }
}

// =============================================================================
// Kernel 2: QB = Q @ bili
// =============================================================================
__global__ void __launch_bounds__(256) qb_kernel(const float* __restrict__ bili)
{
    const int mt = blockIdx.x, h = blockIdx.y, s = blockIdx.z;
    const int m0 = mt * 64;
    const int b = m0 >> 9, l0 = m0 & 511;
    const float* qbase = g_Q + (size_t)(b*HH + h) * LL * DD;
    const float* Bm    = bili + (size_t)(s*HH + h) * DD * DD;
    float* dst         = g_QB + (size_t)((s*BB + b)*HH + h) * LL * DD;

    __shared__ __align__(16) float As[16 * 68];
    __shared__ __align__(16) float Bs[16 * 68];

    const int t = threadIdx.x;
    const int mload = t >> 2, kv = t & 3;
    const int kl = t >> 4, nv = t & 15;
    const int ty = t >> 4, tx = t & 15;

    float c[4][4];
#pragma unroll
    for (int i = 0; i < 4; i++)
#pragma unroll
        for (int j = 0; j < 4; j++) c[i][j] = 0.f;

    for (int k0 = 0; k0 < DD; k0 += 16) {
        float4 a4 = *(const float4*)(qbase + (size_t)(l0 + mload) * DD + k0 + kv * 4);
        As[(kv*4+0)*68 + mload] = a4.x;
        As[(kv*4+1)*68 + mload] = a4.y;
        As[(kv*4+2)*68 + mload] = a4.z;
        As[(kv*4+3)*68 + mload] = a4.w;
        float4 b4 = *(const float4*)(Bm + (size_t)(k0 + kl) * DD + nv * 4);
        Bs[kl*68 + nv*4+0] = b4.x;
        Bs[kl*68 + nv*4+1] = b4.y;
        Bs[kl*68 + nv*4+2] = b4.z;
        Bs[kl*68 + nv*4+3] = b4.w;
        __syncthreads();
#pragma unroll
        for (int k = 0; k < 16; k++) {
            float4 av4 = *(const float4*)&As[k*68 + ty*4];
            float4 bv4 = *(const float4*)&Bs[k*68 + tx*4];
            float a[4] = {av4.x, av4.y, av4.z, av4.w};
            float bb[4] = {bv4.x, bv4.y, bv4.z, bv4.w};
#pragma unroll
            for (int i = 0; i < 4; i++)
#pragma unroll
                for (int j = 0; j < 4; j++) c[i][j] += a[i] * bb[j];
        }
        __syncthreads();
    }

#pragma unroll
    for (int i = 0; i < 4; i++)
#pragma unroll
        for (int j = 0; j < 4; j++)
            dst[(size_t)(l0 + ty*4 + i) * DD + tx*4 + j] = c[i][j];
}

// =============================================================================
// Kernel 3: fused attention. 512 threads = 16 warps; warp owns 4 rows.
// Register-lean (target <=128/thread for full 16-warp residency).
// =============================================================================
#define ATTN_SMEM_FLOATS (6*64*64 + 128*66 + 64*130 + 64*132)

__device__ __forceinline__ float warp_max(float v) {
#pragma unroll
    for (int off = 16; off > 0; off >>= 1)
        v = fmaxf(v, __shfl_xor_sync(0xffffffffu, v, off));
    return v;
}
__device__ __forceinline__ float warp_sum(float v) {
#pragma unroll
    for (int off = 16; off > 0; off >>= 1)
        v += __shfl_xor_sync(0xffffffffu, v, off);
    return v;
}

__global__ void __launch_bounds__(512) attn_kernel(
    const float* __restrict__ amask,   // [B,1,1,L]
    const float* __restrict__ absb,    // [S,H]
    float* __restrict__ out)           // [B,L,H*D]
{
    extern __shared__ float sh[];
    float* qall  = sh;                      // 24576
    float* kt    = sh + 6*64*64;            // [j][d] pad 66 : 8448
    float* vt    = kt + 128*66;             // [d][j] pad 130: 8320
    float* probs = vt + 64*130;             // [row][j] pad 132: 8448

    const int t    = threadIdx.x;
    const int w    = t >> 5;                // 0..15
    const int lane = t & 31;
    const int bh   = blockIdx.y;
    const int b = bh / HH, h = bh % HH;
    const int i0 = blockIdx.x * 64;

    const float* Qb = g_Q + (size_t)bh * LL * DD;
    const float* Kb = g_K + (size_t)bh * LL * DD;
    const float* Vb = g_V + (size_t)bh * LL * DD;

    for (int f = t; f < 6 * 64 * 16; f += 512) {
        int c = f >> 10;
        int r = (f >> 4) & 63;
        int dv = f & 15;
        const float* src = (c == 0)
            ? (Qb + (size_t)(i0 + r) * DD + dv * 4)
            : (g_QB + (size_t)((c - 1) * BB + b) * HH * LL * DD
                    + (size_t)h * LL * DD + (size_t)(i0 + r) * DD + dv * 4);
        float4 v4 = *(const float4*)src;
        float* dp = qall + (c * 64 + r) * 64 + dv * 4;
        dp[0] = v4.x; dp[1] = v4.y; dp[2] = v4.z; dp[3] = v4.w;
    }

    float ab[NSTRUCT];
#pragma unroll
    for (int s = 0; s < NSTRUCT; ++s) ab[s] = __ldg(absb + s*HH + h);

    float mrow[4], lrow[4];
    ull ctx2[4][2];
#pragma unroll
    for (int i = 0; i < 4; ++i) {
        mrow[i] = -1e30f; lrow[i] = 0.f;
        ctx2[i][0] = 0ULL; ctx2[i][1] = 0ULL;
    }

    const int row0 = w * 4;

    for (int jt = 0; jt < 4; ++jt) {
        const int j0 = jt * 128;
        __syncthreads();
        for (int f = t; f < 2048; f += 512) {
            int j = f >> 4, dv = f & 15;
            float4 k4 = *(const float4*)(Kb + (size_t)(j0 + j) * DD + dv * 4);
            float* kp = &kt[j * 66 + dv * 4];
            *(float2*)(kp)     = make_float2(k4.x, k4.y);
            *(float2*)(kp + 2) = make_float2(k4.z, k4.w);
            float4 v4 = *(const float4*)(Vb + (size_t)(j0 + j) * DD + dv * 4);
            vt[(dv*4+0)*130 + j] = v4.x;
            vt[(dv*4+1)*130 + j] = v4.y;
            vt[(dv*4+2)*130 + j] = v4.z;
            vt[(dv*4+3)*130 + j] = v4.w;
        }
        __syncthreads();

        float sreg[4][4];

        for (int c = 0; c < 6; ++c) {
            ull acc2[4][4];
#pragma unroll
            for (int i = 0; i < 4; ++i)
#pragma unroll
                for (int j = 0; j < 4; ++j) acc2[i][j] = 0ULL;

            const float* qc = qall + (c * 64 + row0) * 64;
#pragma unroll 4
            for (int d4 = 0; d4 < 16; ++d4) {
                ull kkA[4], kkB[4];
#pragma unroll
                for (int jj = 0; jj < 4; ++jj) {
                    const float* kp = &kt[(lane + 32*jj) * 66 + d4 * 4];
                    kkA[jj] = *(const ull*)(kp);
                    kkB[jj] = *(const ull*)(kp + 2);
                }
#pragma unroll
                for (int ii = 0; ii < 4; ++ii) {
                    const ull* qp = (const ull*)(qc + ii * 64 + d4 * 4);
                    ull q01 = qp[0];
                    ull q23 = qp[1];
#pragma unroll
                    for (int jj = 0; jj < 4; ++jj) {
                        fma2(acc2[ii][jj], q01, kkA[jj]);
                        fma2(acc2[ii][jj], q23, kkB[jj]);
                    }
                }
            }

            if (c == 0) {
#pragma unroll
                for (int ii = 0; ii < 4; ++ii)
#pragma unroll
                    for (int jj = 0; jj < 4; ++jj) {
                        float2 v = unpack2(acc2[ii][jj]);
                        sreg[ii][jj] = v.x + v.y;
                    }
            } else {
                const float abs_s = ab[c - 1];
                const int s = c - 1;
#pragma unroll
                for (int ii = 0; ii < 4; ++ii) {
                    const unsigned* mp = g_MB
                        + ((size_t)(s*BB + b) * LL + (i0 + row0 + ii)) * 16 + jt * 4;
                    uint4 mw = *(const uint4*)mp;
                    unsigned mj[4] = {mw.x, mw.y, mw.z, mw.w};
#pragma unroll
                    for (int jj = 0; jj < 4; ++jj) {
                        float sel = (float)((mj[jj] >> lane) & 1u);
                        float2 v = unpack2(acc2[ii][jj]);
                        sreg[ii][jj] += sel * (v.x + v.y + abs_s);
                    }
                }
            }
        }

        // ---- online softmax update ----
        float amv[4];
#pragma unroll
        for (int jj = 0; jj < 4; ++jj)
            amv[jj] = __ldg(amask + (size_t)b * LL + j0 + lane + 32*jj);

#pragma unroll
        for (int ii = 0; ii < 4; ++ii) {
            float lg[4];
            float mt = -1e30f;
#pragma unroll
            for (int jj = 0; jj < 4; ++jj) {
                lg[jj] = sreg[ii][jj] * 0.125f + amv[jj];
                mt = fmaxf(mt, lg[jj]);
            }
            mt = warp_max(mt);
            float mnew = fmaxf(mrow[ii], mt);
            float corr = __expf(mrow[ii] - mnew);
            mrow[ii] = mnew;
            float psum = 0.f;
#pragma unroll
            for (int jj = 0; jj < 4; ++jj) {
                float p = __expf(lg[jj] - mnew);
                probs[(row0 + ii) * 132 + lane + 32*jj] = p;
                psum += p;
            }
            psum = warp_sum(psum);
            lrow[ii] = lrow[ii] * corr + psum;
            ull c2 = pack2(corr, corr);
            mul2(ctx2[ii][0], c2);
            mul2(ctx2[ii][1], c2);
        }
        __syncwarp();

        // ---- PV ----
        const float* vr0 = &vt[lane * 130];
        const float* vr1 = &vt[(lane + 32) * 130];
#pragma unroll 4
        for (int j2 = 0; j2 < 64; ++j2) {
            ull vv0 = *(const ull*)(vr0 + 2*j2);
            ull vv1 = *(const ull*)(vr1 + 2*j2);
#pragma unroll
            for (int ii = 0; ii < 4; ++ii) {
                ull pp = *(const ull*)&probs[(row0 + ii) * 132 + 2*j2];
                fma2(ctx2[ii][0], pp, vv0);
                fma2(ctx2[ii][1], pp, vv1);
            }
        }
    }

    // ---- finalize ----
#pragma unroll
    for (int ii = 0; ii < 4; ++ii) {
        const int ig = i0 + row0 + ii;
        float inv = 1.f / lrow[ii];
        float* op = out + (size_t)(b * LL + ig) * (HH*DD) + h * DD;
        float2 c0 = unpack2(ctx2[ii][0]);
        float2 c1 = unpack2(ctx2[ii][1]);
        op[lane]      = (c0.x + c0.y) * inv;
        op[lane + 32] = (c1.x + c1.y) * inv;
    }
}

// =============================================================================
extern "C" void kernel_launch(void* const* d_in, const int* in_sizes, int n_in,
                              void* d_out, int out_size)
{
    const float* hs   = (const float*)d_in[0];
    const float* am   = (const float*)d_in[1];
    const float* smk  = (const float*)d_in[2];
    const float* Wq   = (const float*)d_in[3];
    const float* bq   = (const float*)d_in[4];
    const float* Wk   = (const float*)d_in[5];
    const float* bk   = (const float*)d_in[6];
    const float* Wv   = (const float*)d_in[7];
    const float* bv   = (const float*)d_in[8];
    const float* bili = (const float*)d_in[9];
    const float* absb = (const float*)d_in[10];
    float* out = (float*)d_out;

    pack_mask<<<(NSTRUCT*BB*LL*LL)/256, 256>>>(smk);
    qkv_kernel<<<dim3(64, 6, 3), 256>>>(hs, Wq, bq, Wk, bk, Wv, bv);
    qb_kernel<<<dim3(128, 12, 5), 256>>>(bili);

    const int smem_bytes = ATTN_SMEM_FLOATS * (int)sizeof(float);
    cudaFuncSetAttribute(attn_kernel, cudaFuncAttributeMaxDynamicSharedMemorySize, smem_bytes);
    attn_kernel<<<dim3(8, 192), 512, smem_bytes>>>(am, absb, out);
}

// round 7
// speedup vs baseline: 1.2317x; 1.2317x over previous
#include <cuda_runtime.h>
#include <cuda_bf16.h>
#include <math.h>
#include <cstdint>

#define BB 16
#define LL 512
#define HIDN 768
#define HH 12
#define DD 64
#define NSTRUCT 5
#define BH (BB*HH)   // 192

typedef unsigned long long ull;

// ---- packed f32x2 helpers ----
__device__ __forceinline__ void fma2(ull &d, ull a, ull b) {
    asm("fma.rn.f32x2 %0, %1, %2, %0;" : "+l"(d) : "l"(a), "l"(b));
}
__device__ __forceinline__ void mul2(ull &d, ull s) {
    asm("mul.rn.f32x2 %0, %0, %1;" : "+l"(d) : "l"(s));
}
__device__ __forceinline__ ull pack2(float lo, float hi) {
    ull r; asm("mov.b64 %0, {%1, %2};" : "=l"(r) : "f"(lo), "f"(hi)); return r;
}
__device__ __forceinline__ float2 unpack2(ull v) {
    float2 r; asm("mov.b64 {%0, %1}, %2;" : "=f"(r.x), "=f"(r.y) : "l"(v)); return r;
}

// ---- warp MMA helpers (base ISA: sm_80+, assembles for sm_103) ----
__device__ __forceinline__ uint32_t smem_u32(const void* p) {
    uint32_t a;
    asm("{ .reg .u64 t; cvta.to.shared.u64 t, %1; cvt.u32.u64 %0, t; }" : "=r"(a) : "l"(p));
    return a;
}
#define LDSM4(r, addr) \
    asm volatile("ldmatrix.sync.aligned.m8n8.x4.shared.b16 {%0,%1,%2,%3}, [%4];" \
        : "=r"((r)[0]), "=r"((r)[1]), "=r"((r)[2]), "=r"((r)[3]) : "r"(addr))

__device__ __forceinline__ void mma_bf16(float* c, const uint32_t* a, const uint32_t* b) {
    asm volatile("mma.sync.aligned.m16n8k16.row.col.f32.bf16.bf16.f32 "
        "{%0,%1,%2,%3}, {%4,%5,%6,%7}, {%8,%9}, {%0,%1,%2,%3};"
        : "+f"(c[0]), "+f"(c[1]), "+f"(c[2]), "+f"(c[3])
        : "r"(a[0]), "r"(a[1]), "r"(a[2]), "r"(a[3]), "r"(b[0]), "r"(b[1]));
}
#define CP_ASYNC16(sa, gp) \
    asm volatile("cp.async.cg.shared.global [%0], [%1], 16;" :: "r"(sa), "l"(gp))
#define CP_COMMIT() asm volatile("cp.async.commit_group;" ::: "memory")
#define CP_WAIT1()  asm volatile("cp.async.wait_group 1;" ::: "memory")
#define CP_WAIT0()  asm volatile("cp.async.wait_group 0;" ::: "memory")

// ---------------- scratch ----------------
__device__ float    g_Q [BH * LL * DD];
__device__ float    g_K [BH * LL * DD];
__device__ float    g_V [BH * LL * DD];
__device__ float    g_QB[NSTRUCT * BH * LL * DD];
__device__ unsigned g_MB[NSTRUCT * BB * LL * (LL/32)];
__device__ __nv_bfloat16 g_hsH[BB*LL*HIDN], g_hsL[BB*LL*HIDN];
__device__ __nv_bfloat16 g_WH [3*HIDN*HIDN], g_WL [3*HIDN*HIDN];

// =============================================================================
// Kernel 0a: pack structure mask to bits.
// =============================================================================
__global__ void __launch_bounds__(256) pack_mask(const float* __restrict__ smask)
{
    size_t e = (size_t)blockIdx.x * 256 + threadIdx.x;
    float v = smask[e];
    unsigned bal = __ballot_sync(0xffffffffu, v != 0.f);
    if ((threadIdx.x & 31) == 0) g_MB[e >> 5] = bal;
}

// =============================================================================
// Kernel 0b/0c: split fp32 -> bf16 hi/lo
// =============================================================================
__device__ __forceinline__ void split2(float a, float b, __nv_bfloat162* H, __nv_bfloat162* L) {
    __nv_bfloat16 ah = __float2bfloat16_rn(a), bh = __float2bfloat16_rn(b);
    __nv_bfloat16 al = __float2bfloat16_rn(a - __bfloat162float(ah));
    __nv_bfloat16 bl = __float2bfloat16_rn(b - __bfloat162float(bh));
    *H = __nv_bfloat162(ah, bh);
    *L = __nv_bfloat162(al, bl);
}
__global__ void __launch_bounds__(256) cvt_hs(const float* __restrict__ hs)
{
    size_t i = (size_t)blockIdx.x * 256 + threadIdx.x;
    float4 v = ((const float4*)hs)[i];
    __nv_bfloat162 h0, l0, h1, l1;
    split2(v.x, v.y, &h0, &l0);
    split2(v.z, v.w, &h1, &l1);
    ((__nv_bfloat162*)g_hsH)[2*i]   = h0;
    ((__nv_bfloat162*)g_hsH)[2*i+1] = h1;
    ((__nv_bfloat162*)g_hsL)[2*i]   = l0;
    ((__nv_bfloat162*)g_hsL)[2*i+1] = l1;
}
__global__ void __launch_bounds__(256) cvt_w(const float* __restrict__ Wq,
                                             const float* __restrict__ Wk,
                                             const float* __restrict__ Wv)
{
    size_t i = (size_t)blockIdx.x * 256 + threadIdx.x;
    const size_t per = (size_t)HIDN*HIDN/4;
    const float* src = (i < per) ? Wq : (i < 2*per) ? Wk : Wv;
    size_t loc = i % per;
    float4 v = ((const float4*)src)[loc];
    __nv_bfloat162 h0, l0, h1, l1;
    split2(v.x, v.y, &h0, &l0);
    split2(v.z, v.w, &h1, &l1);
    ((__nv_bfloat162*)g_WH)[2*i]   = h0;
    ((__nv_bfloat162*)g_WH)[2*i+1] = h1;
    ((__nv_bfloat162*)g_WL)[2*i]   = l0;
    ((__nv_bfloat162*)g_WL)[2*i+1] = l1;
}

// =============================================================================
// Kernel 1: QKV projection on mma.sync bf16 (split bf16x3).
// Tile 128(m) x 128(n), K-chunks of 32, 2-stage cp.async pipeline.
// 8 warps; warp (wm,wn) owns 64x32 C: 4x4 m16n8k16 frags.
// Terms accumulated in fp32: Ah*Bh + Ah*Bl + Al*Bh.
// smem per stage: AH|AL|BH|BL, each 128 rows x 32 bf16, row stride 40 bf16 (80B).
// =============================================================================
#define QT_ROWB 80                    // bytes per smem row
#define QT_TILE (128 * QT_ROWB)       // 10240 B
#define QT_STAGE (4 * QT_TILE)        // 40960 B
#define QT_SMEM (2 * QT_STAGE)        // 81920 B
#define NCHUNK (HIDN / 32)            // 24

__global__ void __launch_bounds__(256) qkv_mma_kernel(
    const float* __restrict__ bq, const float* __restrict__ bk, const float* __restrict__ bv)
{
    extern __shared__ __align__(16) char smem[];
    const uint32_t sb = smem_u32(smem);

    const int t = threadIdx.x, wid = t >> 5, lane = t & 31;
    const int m0 = blockIdx.x * 128;
    const int n0 = blockIdx.y * 128;
    const int z  = blockIdx.z;
    const float* bias = (z == 0) ? bq : (z == 1) ? bk : bv;
    float* dst        = (z == 0) ? g_Q : (z == 1) ? g_K : g_V;
    const __nv_bfloat16* BHg = g_WH + (size_t)z * HIDN * HIDN;
    const __nv_bfloat16* BLg = g_WL + (size_t)z * HIDN * HIDN;

    const int wm = (wid & 1) * 64;    // warp m offset in tile
    const int wn = (wid >> 1) * 32;   // warp n offset in tile

    float C[4][4][4];
#pragma unroll
    for (int i = 0; i < 4; i++)
#pragma unroll
        for (int j = 0; j < 4; j++)
#pragma unroll
            for (int k = 0; k < 4; k++) C[i][j][k] = 0.f;

    // ldmatrix per-thread row/col (byte offsets within a tile)
    const uint32_t a_off = (uint32_t)((wm + (lane & 7) + ((lane >> 3) & 1) * 8) * QT_ROWB
                                      + ((lane >> 4) * 8) * 2);
    const uint32_t b_off = (uint32_t)((wn + (lane & 7) + (lane >> 4) * 8) * QT_ROWB
                                      + (((lane >> 3) & 1) * 8) * 2);

    // loader indices: thread covers 2 rows-parts per tile per stage
    const int lr0 = t >> 2, lu0 = t & 3;          // f = t      -> row t/4, quad t%4
    const int lr1 = (t + 256) >> 2, lu1 = t & 3;  // f = t+256

    // ---- issue stage 0 ----
    {
        const int k0 = 0;
        uint32_t s0 = sb;
#pragma unroll
        for (int p = 0; p < 2; ++p) {
            int r = p ? lr1 : lr0, u = p ? lu1 : lu0;
            uint32_t so = (uint32_t)(r * QT_ROWB + u * 16);
            size_t ga = (size_t)(m0 + r) * HIDN + k0 + u * 8;
            size_t gb = (size_t)(n0 + r) * HIDN + k0 + u * 8;
            CP_ASYNC16(s0 + 0*QT_TILE + so, g_hsH + ga);
            CP_ASYNC16(s0 + 1*QT_TILE + so, g_hsL + ga);
            CP_ASYNC16(s0 + 2*QT_TILE + so, BHg + gb);
            CP_ASYNC16(s0 + 3*QT_TILE + so, BLg + gb);
        }
        CP_COMMIT();
    }

    for (int ch = 0; ch < NCHUNK; ++ch) {
        // issue next stage (safe: that buffer's readers finished 1 iter ago)
        if (ch + 1 < NCHUNK) {
            const int k0 = (ch + 1) * 32;
            uint32_t s1 = sb + ((ch + 1) & 1) * QT_STAGE;
#pragma unroll
            for (int p = 0; p < 2; ++p) {
                int r = p ? lr1 : lr0, u = p ? lu1 : lu0;
                uint32_t so = (uint32_t)(r * QT_ROWB + u * 16);
                size_t ga = (size_t)(m0 + r) * HIDN + k0 + u * 8;
                size_t gb = (size_t)(n0 + r) * HIDN + k0 + u * 8;
                CP_ASYNC16(s1 + 0*QT_TILE + so, g_hsH + ga);
                CP_ASYNC16(s1 + 1*QT_TILE + so, g_hsL + ga);
                CP_ASYNC16(s1 + 2*QT_TILE + so, BHg + gb);
                CP_ASYNC16(s1 + 3*QT_TILE + so, BLg + gb);
            }
            CP_COMMIT();
            CP_WAIT1();
        } else {
            CP_WAIT0();
        }
        __syncthreads();

        const uint32_t st = sb + (ch & 1) * QT_STAGE;
        const uint32_t aH = st + 0*QT_TILE + a_off;
        const uint32_t aL = st + 1*QT_TILE + a_off;
        const uint32_t bHb = st + 2*QT_TILE + b_off;
        const uint32_t bLb = st + 3*QT_TILE + b_off;

#pragma unroll
        for (int ks = 0; ks < 2; ++ks) {
            const uint32_t ko = ks * 32;   // 16 bf16 = 32 bytes
            uint32_t ah[4][4], al[4][4], bh[4][2], bl[4][2];
#pragma unroll
            for (int mt = 0; mt < 4; ++mt) {
                LDSM4(ah[mt], aH + mt * 16 * QT_ROWB + ko);
                LDSM4(al[mt], aL + mt * 16 * QT_ROWB + ko);
            }
#pragma unroll
            for (int p = 0; p < 2; ++p) {
                uint32_t r4[4];
                LDSM4(r4, bHb + p * 16 * QT_ROWB + ko);
                bh[2*p][0] = r4[0]; bh[2*p][1] = r4[1];
                bh[2*p+1][0] = r4[2]; bh[2*p+1][1] = r4[3];
                LDSM4(r4, bLb + p * 16 * QT_ROWB + ko);
                bl[2*p][0] = r4[0]; bl[2*p][1] = r4[1];
                bl[2*p+1][0] = r4[2]; bl[2*p+1][1] = r4[3];
            }
#pragma unroll
            for (int mt = 0; mt < 4; ++mt)
#pragma unroll
                for (int nt = 0; nt < 4; ++nt) {
                    mma_bf16(C[mt][nt], ah[mt], bh[nt]);
                    mma_bf16(C[mt][nt], ah[mt], bl[nt]);
                    mma_bf16(C[mt][nt], al[mt], bh[nt]);
                }
        }
        __syncthreads();
    }

    // ---- epilogue ----
#pragma unroll
    for (int mt = 0; mt < 4; ++mt) {
        const int m = m0 + wm + mt * 16 + (lane >> 2);
        const int b = m >> 9, l = m & 511;
#pragma unroll
        for (int nt = 0; nt < 4; ++nt) {
            const int n = n0 + wn + nt * 8 + (lane & 3) * 2;
            const int h = n >> 6, d = n & 63;
            const float b0 = __ldg(bias + n), b1 = __ldg(bias + n + 1);
            float* dp = dst + ((size_t)(b * HH + h) * LL + l) * DD + d;
            *(float2*)dp = make_float2(C[mt][nt][0] + b0, C[mt][nt][1] + b1);
            float* dp2 = dst + ((size_t)(b * HH + h) * LL + (l + 8)) * DD + d;
            *(float2*)dp2 = make_float2(C[mt][nt][2] + b0, C[mt][nt][3] + b1);
        }
    }
}

// =============================================================================
// Kernel 2: QB = Q @ bili (SIMT)
// =============================================================================
__global__ void __launch_bounds__(256) qb_kernel(const float* __restrict__ bili)
{
    const int mt = blockIdx.x, h = blockIdx.y, s = blockIdx.z;
    const int m0 = mt * 64;
    const int b = m0 >> 9, l0 = m0 & 511;
    const float* qbase = g_Q + (size_t)(b*HH + h) * LL * DD;
    const float* Bm    = bili + (size_t)(s*HH + h) * DD * DD;
    float* dst         = g_QB + (size_t)((s*BB + b)*HH + h) * LL * DD;

    __shared__ __align__(16) float As[16 * 68];
    __shared__ __align__(16) float Bs[16 * 68];

    const int t = threadIdx.x;
    const int mload = t >> 2, kv = t & 3;
    const int kl = t >> 4, nv = t & 15;
    const int ty = t >> 4, tx = t & 15;

    float c[4][4];
#pragma unroll
    for (int i = 0; i < 4; i++)
#pragma unroll
        for (int j = 0; j < 4; j++) c[i][j] = 0.f;

    for (int k0 = 0; k0 < DD; k0 += 16) {
        float4 a4 = *(const float4*)(qbase + (size_t)(l0 + mload) * DD + k0 + kv * 4);
        As[(kv*4+0)*68 + mload] = a4.x;
        As[(kv*4+1)*68 + mload] = a4.y;
        As[(kv*4+2)*68 + mload] = a4.z;
        As[(kv*4+3)*68 + mload] = a4.w;
        float4 b4 = *(const float4*)(Bm + (size_t)(k0 + kl) * DD + nv * 4);
        Bs[kl*68 + nv*4+0] = b4.x;
        Bs[kl*68 + nv*4+1] = b4.y;
        Bs[kl*68 + nv*4+2] = b4.z;
        Bs[kl*68 + nv*4+3] = b4.w;
        __syncthreads();
#pragma unroll
        for (int k = 0; k < 16; k++) {
            float4 av4 = *(const float4*)&As[k*68 + ty*4];
            float4 bv4 = *(const float4*)&Bs[k*68 + tx*4];
            float a[4] = {av4.x, av4.y, av4.z, av4.w};
            float bb[4] = {bv4.x, bv4.y, bv4.z, bv4.w};
#pragma unroll
            for (int i = 0; i < 4; i++)
#pragma unroll
                for (int j = 0; j < 4; j++) c[i][j] += a[i] * bb[j];
        }
        __syncthreads();
    }

#pragma unroll
    for (int i = 0; i < 4; i++)
#pragma unroll
        for (int j = 0; j < 4; j++)
            dst[(size_t)(l0 + ty*4 + i) * DD + tx*4 + j] = c[i][j];
}

// =============================================================================
// Kernel 3: fused attention (R4 config: 256 thr, warp owns 8 rows, FFMA2).
// =============================================================================
#define ATTN_SMEM_FLOATS (6*64*64 + 128*66 + 64*130 + 64*132)

__device__ __forceinline__ float warp_max(float v) {
#pragma unroll
    for (int off = 16; off > 0; off >>= 1)
        v = fmaxf(v, __shfl_xor_sync(0xffffffffu, v, off));
    return v;
}
__device__ __forceinline__ float warp_sum(float v) {
#pragma unroll
    for (int off = 16; off > 0; off >>= 1)
        v += __shfl_xor_sync(0xffffffffu, v, off);
    return v;
}

__global__ void __launch_bounds__(256) attn_kernel(
    const float* __restrict__ amask,
    const float* __restrict__ absb,
    float* __restrict__ out)
{
    extern __shared__ float sh[];
    float* qall  = sh;
    float* kt    = sh + 6*64*64;
    float* vt    = kt + 128*66;
    float* probs = vt + 64*130;

    const int t    = threadIdx.x;
    const int w    = t >> 5;
    const int lane = t & 31;
    const int bh   = blockIdx.y;
    const int b = bh / HH, h = bh % HH;
    const int i0 = blockIdx.x * 64;

    const float* Qb = g_Q + (size_t)bh * LL * DD;
    const float* Kb = g_K + (size_t)bh * LL * DD;
    const float* Vb = g_V + (size_t)bh * LL * DD;

    for (int f = t; f < 6 * 64 * 16; f += 256) {
        int c = f >> 10;
        int r = (f >> 4) & 63;
        int dv = f & 15;
        const float* src = (c == 0)
            ? (Qb + (size_t)(i0 + r) * DD + dv * 4)
            : (g_QB + (size_t)((c - 1) * BB + b) * HH * LL * DD
                    + (size_t)h * LL * DD + (size_t)(i0 + r) * DD + dv * 4);
        float4 v4 = *(const float4*)src;
        float* dp = qall + (c * 64 + r) * 64 + dv * 4;
        dp[0] = v4.x; dp[1] = v4.y; dp[2] = v4.z; dp[3] = v4.w;
    }

    float ab[NSTRUCT];
#pragma unroll
    for (int s = 0; s < NSTRUCT; ++s) ab[s] = __ldg(absb + s*HH + h);

    float mrow[8], lrow[8];
    ull ctx2[8][2];
#pragma unroll
    for (int i = 0; i < 8; ++i) {
        mrow[i] = -1e30f; lrow[i] = 0.f;
        ctx2[i][0] = 0ULL; ctx2[i][1] = 0ULL;
    }

    const int row0 = w * 8;

    for (int jt = 0; jt < 4; ++jt) {
        const int j0 = jt * 128;
        __syncthreads();
        for (int f = t; f < 2048; f += 256) {
            int j = f >> 4, dv = f & 15;
            float4 k4 = *(const float4*)(Kb + (size_t)(j0 + j) * DD + dv * 4);
            float* kp = &kt[j * 66 + dv * 4];
            *(float2*)(kp)     = make_float2(k4.x, k4.y);
            *(float2*)(kp + 2) = make_float2(k4.z, k4.w);
            float4 v4 = *(const float4*)(Vb + (size_t)(j0 + j) * DD + dv * 4);
            vt[(dv*4+0)*130 + j] = v4.x;
            vt[(dv*4+1)*130 + j] = v4.y;
            vt[(dv*4+2)*130 + j] = v4.z;
            vt[(dv*4+3)*130 + j] = v4.w;
        }
        __syncthreads();

        float sreg[8][4];

        for (int c = 0; c < 6; ++c) {
            ull acc2[8][4];
#pragma unroll
            for (int i = 0; i < 8; ++i)
#pragma unroll
                for (int j = 0; j < 4; ++j) acc2[i][j] = 0ULL;

            const float* qc = qall + (c * 64 + row0) * 64;
#pragma unroll 4
            for (int d4 = 0; d4 < 16; ++d4) {
                ull kkA[4], kkB[4];
#pragma unroll
                for (int jj = 0; jj < 4; ++jj) {
                    const float* kp = &kt[(lane + 32*jj) * 66 + d4 * 4];
                    kkA[jj] = *(const ull*)(kp);
                    kkB[jj] = *(const ull*)(kp + 2);
                }
#pragma unroll
                for (int ii = 0; ii < 8; ++ii) {
                    const ull* qp = (const ull*)(qc + ii * 64 + d4 * 4);
                    ull q01 = qp[0];
                    ull q23 = qp[1];
#pragma unroll
                    for (int jj = 0; jj < 4; ++jj) {
                        fma2(acc2[ii][jj], q01, kkA[jj]);
                        fma2(acc2[ii][jj], q23, kkB[jj]);
                    }
                }
            }

            if (c == 0) {
#pragma unroll
                for (int ii = 0; ii < 8; ++ii)
#pragma unroll
                    for (int jj = 0; jj < 4; ++jj) {
                        float2 v = unpack2(acc2[ii][jj]);
                        sreg[ii][jj] = v.x + v.y;
                    }
            } else {
                const float abs_s = ab[c - 1];
                const int s = c - 1;
#pragma unroll
                for (int ii = 0; ii < 8; ++ii) {
                    const unsigned* mp = g_MB
                        + ((size_t)(s*BB + b) * LL + (i0 + row0 + ii)) * 16 + jt * 4;
                    uint4 mw = *(const uint4*)mp;
                    unsigned mj[4] = {mw.x, mw.y, mw.z, mw.w};
#pragma unroll
                    for (int jj = 0; jj < 4; ++jj) {
                        float sel = (float)((mj[jj] >> lane) & 1u);
                        float2 v = unpack2(acc2[ii][jj]);
                        sreg[ii][jj] += sel * (v.x + v.y + abs_s);
                    }
                }
            }
        }

        float amv[4];
#pragma unroll
        for (int jj = 0; jj < 4; ++jj)
            amv[jj] = __ldg(amask + (size_t)b * LL + j0 + lane + 32*jj);

#pragma unroll
        for (int ii = 0; ii < 8; ++ii) {
            float lg[4];
            float mt = -1e30f;
#pragma unroll
            for (int jj = 0; jj < 4; ++jj) {
                lg[jj] = sreg[ii][jj] * 0.125f + amv[jj];
                mt = fmaxf(mt, lg[jj]);
            }
            mt = warp_max(mt);
            float mnew = fmaxf(mrow[ii], mt);
            float corr = __expf(mrow[ii] - mnew);
            mrow[ii] = mnew;
            float psum = 0.f;
#pragma unroll
            for (int jj = 0; jj < 4; ++jj) {
                float p = __expf(lg[jj] - mnew);
                probs[(row0 + ii) * 132 + lane + 32*jj] = p;
                psum += p;
            }
            psum = warp_sum(psum);
            lrow[ii] = lrow[ii] * corr + psum;
            ull c2 = pack2(corr, corr);
            mul2(ctx2[ii][0], c2);
            mul2(ctx2[ii][1], c2);
        }
        __syncwarp();

        const float* vr0 = &vt[lane * 130];
        const float* vr1 = &vt[(lane + 32) * 130];
#pragma unroll 2
        for (int j2 = 0; j2 < 64; ++j2) {
            ull vv0 = *(const ull*)(vr0 + 2*j2);
            ull vv1 = *(const ull*)(vr1 + 2*j2);
#pragma unroll
            for (int ii = 0; ii < 8; ++ii) {
                ull pp = *(const ull*)&probs[(row0 + ii) * 132 + 2*j2];
                fma2(ctx2[ii][0], pp, vv0);
                fma2(ctx2[ii][1], pp, vv1);
            }
        }
    }

#pragma unroll
    for (int ii = 0; ii < 8; ++ii) {
        const int ig = i0 + row0 + ii;
        float inv = 1.f / lrow[ii];
        float* op = out + (size_t)(b * LL + ig) * (HH*DD) + h * DD;
        float2 c0 = unpack2(ctx2[ii][0]);
        float2 c1 = unpack2(ctx2[ii][1]);
        op[lane]      = (c0.x + c0.y) * inv;
        op[lane + 32] = (c1.x + c1.y) * inv;
    }
}

// =============================================================================
extern "C" void kernel_launch(void* const* d_in, const int* in_sizes, int n_in,
                              void* d_out, int out_size)
{
    const float* hs   = (const float*)d_in[0];
    const float* am   = (const float*)d_in[1];
    const float* smk  = (const float*)d_in[2];
    const float* Wq   = (const float*)d_in[3];
    const float* bq   = (const float*)d_in[4];
    const float* Wk   = (const float*)d_in[5];
    const float* bk   = (const float*)d_in[6];
    const float* Wv   = (const float*)d_in[7];
    const float* bv   = (const float*)d_in[8];
    const float* bili = (const float*)d_in[9];
    const float* absb = (const float*)d_in[10];
    float* out = (float*)d_out;

    pack_mask<<<(NSTRUCT*BB*LL*LL)/256, 256>>>(smk);
    cvt_hs<<<(BB*LL*HIDN/4)/256, 256>>>(hs);
    cvt_w<<<(3*HIDN*HIDN/4)/256, 256>>>(Wq, Wk, Wv);

    cudaFuncSetAttribute(qkv_mma_kernel, cudaFuncAttributeMaxDynamicSharedMemorySize, QT_SMEM);
    qkv_mma_kernel<<<dim3(64, 6, 3), 256, QT_SMEM>>>(bq, bk, bv);

    qb_kernel<<<dim3(128, 12, 5), 256>>>(bili);

    const int smem_bytes = ATTN_SMEM_FLOATS * (int)sizeof(float);
    cudaFuncSetAttribute(attn_kernel, cudaFuncAttributeMaxDynamicSharedMemorySize, smem_bytes);
    attn_kernel<<<dim3(8, 192), 256, smem_bytes>>>(am, absb, out);
}

// round 8
// speedup vs baseline: 1.7692x; 1.4364x over previous
#include <cuda_runtime.h>
#include <cuda_bf16.h>
#include <math.h>
#include <cstdint>

#define BB 16
#define LL 512
#define HIDN 768
#define HH 12
#define DD 64
#define NSTRUCT 5
#define BH (BB*HH)   // 192

typedef unsigned long long ull;

// ---- packed f32x2 helpers ----
__device__ __forceinline__ void fma2(ull &d, ull a, ull b) {
    asm("fma.rn.f32x2 %0, %1, %2, %0;" : "+l"(d) : "l"(a), "l"(b));
}
__device__ __forceinline__ void mul2(ull &d, ull s) {
    asm("mul.rn.f32x2 %0, %0, %1;" : "+l"(d) : "l"(s));
}
__device__ __forceinline__ ull pack2(float lo, float hi) {
    ull r; asm("mov.b64 %0, {%1, %2};" : "=l"(r) : "f"(lo), "f"(hi)); return r;
}
__device__ __forceinline__ float2 unpack2(ull v) {
    float2 r; asm("mov.b64 {%0, %1}, %2;" : "=f"(r.x), "=f"(r.y) : "l"(v)); return r;
}

// ---- warp MMA helpers ----
__device__ __forceinline__ uint32_t smem_u32(const void* p) {
    uint32_t a;
    asm("{ .reg .u64 t; cvta.to.shared.u64 t, %1; cvt.u32.u64 %0, t; }" : "=r"(a) : "l"(p));
    return a;
}
#define LDSM4(r, addr) \
    asm volatile("ldmatrix.sync.aligned.m8n8.x4.shared.b16 {%0,%1,%2,%3}, [%4];" \
        : "=r"((r)[0]), "=r"((r)[1]), "=r"((r)[2]), "=r"((r)[3]) : "r"(addr))

__device__ __forceinline__ void mma_bf16(float* c, const uint32_t* a, const uint32_t* b) {
    asm volatile("mma.sync.aligned.m16n8k16.row.col.f32.bf16.bf16.f32 "
        "{%0,%1,%2,%3}, {%4,%5,%6,%7}, {%8,%9}, {%0,%1,%2,%3};"
        : "+f"(c[0]), "+f"(c[1]), "+f"(c[2]), "+f"(c[3])
        : "r"(a[0]), "r"(a[1]), "r"(a[2]), "r"(a[3]), "r"(b[0]), "r"(b[1]));
}
#define CP_ASYNC16(sa, gp) \
    asm volatile("cp.async.cg.shared.global [%0], [%1], 16;" :: "r"(sa), "l"(gp))
#define CP_COMMIT() asm volatile("cp.async.commit_group;" ::: "memory")
#define CP_WAIT1()  asm volatile("cp.async.wait_group 1;" ::: "memory")
#define CP_WAIT0()  asm volatile("cp.async.wait_group 0;" ::: "memory")

// ---------------- scratch ----------------
__device__ float    g_Q [BH * LL * DD];
__device__ float    g_K [BH * LL * DD];
__device__ float    g_V [BH * LL * DD];
__device__ float    g_QB[NSTRUCT * BH * LL * DD];
__device__ unsigned g_MB[NSTRUCT * BB * LL * (LL/32)];
__device__ __nv_bfloat16 g_hsH[BB*LL*HIDN], g_hsL[BB*LL*HIDN];
__device__ __nv_bfloat16 g_WH [3*HIDN*HIDN], g_WL [3*HIDN*HIDN];

// =============================================================================
// Kernel 0a: pack structure mask to bits.
// =============================================================================
__global__ void __launch_bounds__(256) pack_mask(const float* __restrict__ smask)
{
    size_t e = (size_t)blockIdx.x * 256 + threadIdx.x;
    float v = smask[e];
    unsigned bal = __ballot_sync(0xffffffffu, v != 0.f);
    if ((threadIdx.x & 31) == 0) g_MB[e >> 5] = bal;
}

// =============================================================================
// Kernel 0b/0c: split fp32 -> bf16 hi/lo
// =============================================================================
__device__ __forceinline__ void split2(float a, float b, __nv_bfloat162* H, __nv_bfloat162* L) {
    __nv_bfloat16 ah = __float2bfloat16_rn(a), bh = __float2bfloat16_rn(b);
    __nv_bfloat16 al = __float2bfloat16_rn(a - __bfloat162float(ah));
    __nv_bfloat16 bl = __float2bfloat16_rn(b - __bfloat162float(bh));
    *H = __nv_bfloat162(ah, bh);
    *L = __nv_bfloat162(al, bl);
}
__global__ void __launch_bounds__(256) cvt_hs(const float* __restrict__ hs)
{
    size_t i = (size_t)blockIdx.x * 256 + threadIdx.x;
    float4 v = ((const float4*)hs)[i];
    __nv_bfloat162 h0, l0, h1, l1;
    split2(v.x, v.y, &h0, &l0);
    split2(v.z, v.w, &h1, &l1);
    ((__nv_bfloat162*)g_hsH)[2*i]   = h0;
    ((__nv_bfloat162*)g_hsH)[2*i+1] = h1;
    ((__nv_bfloat162*)g_hsL)[2*i]   = l0;
    ((__nv_bfloat162*)g_hsL)[2*i+1] = l1;
}
__global__ void __launch_bounds__(256) cvt_w(const float* __restrict__ Wq,
                                             const float* __restrict__ Wk,
                                             const float* __restrict__ Wv)
{
    size_t i = (size_t)blockIdx.x * 256 + threadIdx.x;
    const size_t per = (size_t)HIDN*HIDN/4;
    const float* src = (i < per) ? Wq : (i < 2*per) ? Wk : Wv;
    size_t loc = i % per;
    float4 v = ((const float4*)src)[loc];
    __nv_bfloat162 h0, l0, h1, l1;
    split2(v.x, v.y, &h0, &l0);
    split2(v.z, v.w, &h1, &l1);
    ((__nv_bfloat162*)g_WH)[2*i]   = h0;
    ((__nv_bfloat162*)g_WH)[2*i+1] = h1;
    ((__nv_bfloat162*)g_WL)[2*i]   = l0;
    ((__nv_bfloat162*)g_WL)[2*i+1] = l1;
}

// =============================================================================
// Kernel 1: QKV projection on mma.sync bf16 (split bf16x3). (unchanged from R7)
// =============================================================================
#define QT_ROWB 80
#define QT_TILE (128 * QT_ROWB)
#define QT_STAGE (4 * QT_TILE)
#define QT_SMEM (2 * QT_STAGE)
#define NCHUNK (HIDN / 32)

__global__ void __launch_bounds__(256) qkv_mma_kernel(
    const float* __restrict__ bq, const float* __restrict__ bk, const float* __restrict__ bv)
{
    extern __shared__ __align__(16) char smem[];
    const uint32_t sb = smem_u32(smem);

    const int t = threadIdx.x, wid = t >> 5, lane = t & 31;
    const int m0 = blockIdx.x * 128;
    const int n0 = blockIdx.y * 128;
    const int z  = blockIdx.z;
    const float* bias = (z == 0) ? bq : (z == 1) ? bk : bv;
    float* dst        = (z == 0) ? g_Q : (z == 1) ? g_K : g_V;
    const __nv_bfloat16* BHg = g_WH + (size_t)z * HIDN * HIDN;
    const __nv_bfloat16* BLg = g_WL + (size_t)z * HIDN * HIDN;

    const int wm = (wid & 1) * 64;
    const int wn = (wid >> 1) * 32;

    float C[4][4][4];
#pragma unroll
    for (int i = 0; i < 4; i++)
#pragma unroll
        for (int j = 0; j < 4; j++)
#pragma unroll
            for (int k = 0; k < 4; k++) C[i][j][k] = 0.f;

    const uint32_t a_off = (uint32_t)((wm + (lane & 7) + ((lane >> 3) & 1) * 8) * QT_ROWB
                                      + ((lane >> 4) * 8) * 2);
    const uint32_t b_off = (uint32_t)((wn + (lane & 7) + (lane >> 4) * 8) * QT_ROWB
                                      + (((lane >> 3) & 1) * 8) * 2);

    const int lr0 = t >> 2, lu0 = t & 3;
    const int lr1 = (t + 256) >> 2, lu1 = t & 3;

    {
        const int k0 = 0;
        uint32_t s0 = sb;
#pragma unroll
        for (int p = 0; p < 2; ++p) {
            int r = p ? lr1 : lr0, u = p ? lu1 : lu0;
            uint32_t so = (uint32_t)(r * QT_ROWB + u * 16);
            size_t ga = (size_t)(m0 + r) * HIDN + k0 + u * 8;
            size_t gb = (size_t)(n0 + r) * HIDN + k0 + u * 8;
            CP_ASYNC16(s0 + 0*QT_TILE + so, g_hsH + ga);
            CP_ASYNC16(s0 + 1*QT_TILE + so, g_hsL + ga);
            CP_ASYNC16(s0 + 2*QT_TILE + so, BHg + gb);
            CP_ASYNC16(s0 + 3*QT_TILE + so, BLg + gb);
        }
        CP_COMMIT();
    }

    for (int ch = 0; ch < NCHUNK; ++ch) {
        if (ch + 1 < NCHUNK) {
            const int k0 = (ch + 1) * 32;
            uint32_t s1 = sb + ((ch + 1) & 1) * QT_STAGE;
#pragma unroll
            for (int p = 0; p < 2; ++p) {
                int r = p ? lr1 : lr0, u = p ? lu1 : lu0;
                uint32_t so = (uint32_t)(r * QT_ROWB + u * 16);
                size_t ga = (size_t)(m0 + r) * HIDN + k0 + u * 8;
                size_t gb = (size_t)(n0 + r) * HIDN + k0 + u * 8;
                CP_ASYNC16(s1 + 0*QT_TILE + so, g_hsH + ga);
                CP_ASYNC16(s1 + 1*QT_TILE + so, g_hsL + ga);
                CP_ASYNC16(s1 + 2*QT_TILE + so, BHg + gb);
                CP_ASYNC16(s1 + 3*QT_TILE + so, BLg + gb);
            }
            CP_COMMIT();
            CP_WAIT1();
        } else {
            CP_WAIT0();
        }
        __syncthreads();

        const uint32_t st = sb + (ch & 1) * QT_STAGE;
        const uint32_t aH = st + 0*QT_TILE + a_off;
        const uint32_t aL = st + 1*QT_TILE + a_off;
        const uint32_t bHb = st + 2*QT_TILE + b_off;
        const uint32_t bLb = st + 3*QT_TILE + b_off;

#pragma unroll
        for (int ks = 0; ks < 2; ++ks) {
            const uint32_t ko = ks * 32;
            uint32_t ah[4][4], al[4][4], bh[4][2], bl[4][2];
#pragma unroll
            for (int mt = 0; mt < 4; ++mt) {
                LDSM4(ah[mt], aH + mt * 16 * QT_ROWB + ko);
                LDSM4(al[mt], aL + mt * 16 * QT_ROWB + ko);
            }
#pragma unroll
            for (int p = 0; p < 2; ++p) {
                uint32_t r4[4];
                LDSM4(r4, bHb + p * 16 * QT_ROWB + ko);
                bh[2*p][0] = r4[0]; bh[2*p][1] = r4[1];
                bh[2*p+1][0] = r4[2]; bh[2*p+1][1] = r4[3];
                LDSM4(r4, bLb + p * 16 * QT_ROWB + ko);
                bl[2*p][0] = r4[0]; bl[2*p][1] = r4[1];
                bl[2*p+1][0] = r4[2]; bl[2*p+1][1] = r4[3];
            }
#pragma unroll
            for (int mt = 0; mt < 4; ++mt)
#pragma unroll
                for (int nt = 0; nt < 4; ++nt) {
                    mma_bf16(C[mt][nt], ah[mt], bh[nt]);
                    mma_bf16(C[mt][nt], ah[mt], bl[nt]);
                    mma_bf16(C[mt][nt], al[mt], bh[nt]);
                }
        }
        __syncthreads();
    }

#pragma unroll
    for (int mt = 0; mt < 4; ++mt) {
        const int m = m0 + wm + mt * 16 + (lane >> 2);
        const int b = m >> 9, l = m & 511;
#pragma unroll
        for (int nt = 0; nt < 4; ++nt) {
            const int n = n0 + wn + nt * 8 + (lane & 3) * 2;
            const int h = n >> 6, d = n & 63;
            const float b0 = __ldg(bias + n), b1 = __ldg(bias + n + 1);
            float* dp = dst + ((size_t)(b * HH + h) * LL + l) * DD + d;
            *(float2*)dp = make_float2(C[mt][nt][0] + b0, C[mt][nt][1] + b1);
            float* dp2 = dst + ((size_t)(b * HH + h) * LL + (l + 8)) * DD + d;
            *(float2*)dp2 = make_float2(C[mt][nt][2] + b0, C[mt][nt][3] + b1);
        }
    }
}

// =============================================================================
// Kernel 2: QB = Q @ bili (SIMT)
// =============================================================================
__global__ void __launch_bounds__(256) qb_kernel(const float* __restrict__ bili)
{
    const int mt = blockIdx.x, h = blockIdx.y, s = blockIdx.z;
    const int m0 = mt * 64;
    const int b = m0 >> 9, l0 = m0 & 511;
    const float* qbase = g_Q + (size_t)(b*HH + h) * LL * DD;
    const float* Bm    = bili + (size_t)(s*HH + h) * DD * DD;
    float* dst         = g_QB + (size_t)((s*BB + b)*HH + h) * LL * DD;

    __shared__ __align__(16) float As[16 * 68];
    __shared__ __align__(16) float Bs[16 * 68];

    const int t = threadIdx.x;
    const int mload = t >> 2, kv = t & 3;
    const int kl = t >> 4, nv = t & 15;
    const int ty = t >> 4, tx = t & 15;

    float c[4][4];
#pragma unroll
    for (int i = 0; i < 4; i++)
#pragma unroll
        for (int j = 0; j < 4; j++) c[i][j] = 0.f;

    for (int k0 = 0; k0 < DD; k0 += 16) {
        float4 a4 = *(const float4*)(qbase + (size_t)(l0 + mload) * DD + k0 + kv * 4);
        As[(kv*4+0)*68 + mload] = a4.x;
        As[(kv*4+1)*68 + mload] = a4.y;
        As[(kv*4+2)*68 + mload] = a4.z;
        As[(kv*4+3)*68 + mload] = a4.w;
        float4 b4 = *(const float4*)(Bm + (size_t)(k0 + kl) * DD + nv * 4);
        Bs[kl*68 + nv*4+0] = b4.x;
        Bs[kl*68 + nv*4+1] = b4.y;
        Bs[kl*68 + nv*4+2] = b4.z;
        Bs[kl*68 + nv*4+3] = b4.w;
        __syncthreads();
#pragma unroll
        for (int k = 0; k < 16; k++) {
            float4 av4 = *(const float4*)&As[k*68 + ty*4];
            float4 bv4 = *(const float4*)&Bs[k*68 + tx*4];
            float a[4] = {av4.x, av4.y, av4.z, av4.w};
            float bb[4] = {bv4.x, bv4.y, bv4.z, bv4.w};
#pragma unroll
            for (int i = 0; i < 4; i++)
#pragma unroll
                for (int j = 0; j < 4; j++) c[i][j] += a[i] * bb[j];
        }
        __syncthreads();
    }

#pragma unroll
    for (int i = 0; i < 4; i++)
#pragma unroll
        for (int j = 0; j < 4; j++)
            dst[(size_t)(l0 + ty*4 + i) * DD + tx*4 + j] = c[i][j];
}

// =============================================================================
// Kernel 3: fused attention with mma.sync scores.
// 256 thr = 8 warps. Warp (w&1, w>>1) owns a 32m x 32n S-fragment per j-tile.
// smem (bytes): qH/qL split q-components (144B row stride), kH/kL K tile,
//               vt fp32 [d][j], sc fp32 [64][132] (scores -> probs in place).
// =============================================================================
#define A_QH 0
#define A_QL (A_QH + 6*64*144)          // 55296
#define A_KH (A_QL + 6*64*144)          // 110592
#define A_KL (A_KH + 128*144)           // 129024
#define A_VT (A_KL + 128*144)           // 147456
#define A_SC (A_VT + 64*130*4)          // 180736
#define A_TOT (A_SC + 64*132*4)         // 214528

__device__ __forceinline__ float warp_max(float v) {
#pragma unroll
    for (int off = 16; off > 0; off >>= 1)
        v = fmaxf(v, __shfl_xor_sync(0xffffffffu, v, off));
    return v;
}
__device__ __forceinline__ float warp_sum(float v) {
#pragma unroll
    for (int off = 16; off > 0; off >>= 1)
        v += __shfl_xor_sync(0xffffffffu, v, off);
    return v;
}

__global__ void __launch_bounds__(256) attn_kernel(
    const float* __restrict__ amask,
    const float* __restrict__ absb,
    float* __restrict__ out)
{
    extern __shared__ __align__(16) char smem[];
    const uint32_t sb = smem_u32(smem);
    float* vt = (float*)(smem + A_VT);
    float* sc = (float*)(smem + A_SC);

    const int t    = threadIdx.x;
    const int w    = t >> 5;
    const int lane = t & 31;
    const int bh   = blockIdx.y;
    const int b = bh / HH, h = bh % HH;
    const int i0 = blockIdx.x * 64;

    const float* Qb = g_Q + (size_t)bh * LL * DD;
    const float* Kb = g_K + (size_t)bh * LL * DD;
    const float* Vb = g_V + (size_t)bh * LL * DD;

    // ---- load q + 5 qb components, split to bf16 hi/lo ----
    for (int f = t; f < 6 * 64 * 16; f += 256) {
        int c = f >> 10;
        int r = (f >> 4) & 63;
        int dv = f & 15;
        const float* src = (c == 0)
            ? (Qb + (size_t)(i0 + r) * DD + dv * 4)
            : (g_QB + (size_t)((c - 1) * BB + b) * HH * LL * DD
                    + (size_t)h * LL * DD + (size_t)(i0 + r) * DD + dv * 4);
        float4 v4 = *(const float4*)src;
        __nv_bfloat162 h0, l0, h1, l1;
        split2(v4.x, v4.y, &h0, &l0);
        split2(v4.z, v4.w, &h1, &l1);
        char* p = smem + (c * 64 + r) * 144 + dv * 8;
        *(__nv_bfloat162*)(p + A_QH)     = h0;
        *(__nv_bfloat162*)(p + A_QH + 4) = h1;
        *(__nv_bfloat162*)(p + A_QL)     = l0;
        *(__nv_bfloat162*)(p + A_QL + 4) = l1;
    }

    float ab[NSTRUCT];
#pragma unroll
    for (int s = 0; s < NSTRUCT; ++s) ab[s] = __ldg(absb + s*HH + h);

    float mrow[8], lrow[8];
    ull ctx2[8][2];
#pragma unroll
    for (int i = 0; i < 8; ++i) {
        mrow[i] = -1e30f; lrow[i] = 0.f;
        ctx2[i][0] = 0ULL; ctx2[i][1] = 0ULL;
    }

    const int row0 = w * 8;              // softmax/PV row ownership
    const int wm = (w & 1) * 32;         // mma m offset
    const int wn = (w >> 1) * 32;        // mma n offset

    // ldmatrix per-thread offsets
    const uint32_t a_base = sb + A_QH
        + (uint32_t)((wm + (lane & 7) + ((lane >> 3) & 1) * 8) * 144 + (lane >> 4) * 16);
    const uint32_t b_base = sb + A_KH
        + (uint32_t)((wn + (lane & 7) + (lane >> 4) * 8) * 144 + ((lane >> 3) & 1) * 16);
    const uint32_t QLOFF = A_QL - A_QH;  // 55296
    const uint32_t KLOFF = A_KL - A_KH;  // 18432

    for (int jt = 0; jt < 4; ++jt) {
        const int j0 = jt * 128;
        __syncthreads();   // previous-tile readers done (vt/sc/k tiles)
        // ---- load K tile (split bf16) + V tile (fp32, [d][j]) ----
        for (int f = t; f < 2048; f += 256) {
            int j = f >> 4, dv = f & 15;
            float4 k4 = *(const float4*)(Kb + (size_t)(j0 + j) * DD + dv * 4);
            __nv_bfloat162 h0, l0, h1, l1;
            split2(k4.x, k4.y, &h0, &l0);
            split2(k4.z, k4.w, &h1, &l1);
            char* p = smem + j * 144 + dv * 8;
            *(__nv_bfloat162*)(p + A_KH)     = h0;
            *(__nv_bfloat162*)(p + A_KH + 4) = h1;
            *(__nv_bfloat162*)(p + A_KL)     = l0;
            *(__nv_bfloat162*)(p + A_KL + 4) = l1;
            float4 v4 = *(const float4*)(Vb + (size_t)(j0 + j) * DD + dv * 4);
            vt[(dv*4+0)*130 + j] = v4.x;
            vt[(dv*4+1)*130 + j] = v4.y;
            vt[(dv*4+2)*130 + j] = v4.z;
            vt[(dv*4+3)*130 + j] = v4.w;
        }
        __syncthreads();

        // ---- MMA: S fragment [2 mt][4 nt][4] ----
        float S[2][4][4];
#pragma unroll
        for (int i = 0; i < 2; ++i)
#pragma unroll
            for (int j = 0; j < 4; ++j)
#pragma unroll
                for (int k = 0; k < 4; ++k) S[i][j][k] = 0.f;

        const int widx = jt * 4 + (wn >> 5);

        for (int c = 0; c < 6; ++c) {
            float Sc[2][4][4];
            float (*acc)[4][4] = (c == 0) ? S : Sc;
            if (c != 0) {
#pragma unroll
                for (int i = 0; i < 2; ++i)
#pragma unroll
                    for (int j = 0; j < 4; ++j)
#pragma unroll
                        for (int k = 0; k < 4; ++k) Sc[i][j][k] = 0.f;
            }
            const uint32_t aH = a_base + (uint32_t)(c * 64 * 144);
#pragma unroll
            for (int ks = 0; ks < 4; ++ks) {
                const uint32_t ko = ks * 32;
                uint32_t ah[2][4], al[2][4], bhf[4][2], blf[4][2];
#pragma unroll
                for (int mt = 0; mt < 2; ++mt) {
                    LDSM4(ah[mt], aH + mt * 16 * 144 + ko);
                    LDSM4(al[mt], aH + QLOFF + mt * 16 * 144 + ko);
                }
#pragma unroll
                for (int p = 0; p < 2; ++p) {
                    uint32_t r4[4];
                    LDSM4(r4, b_base + p * 16 * 144 + ko);
                    bhf[2*p][0] = r4[0]; bhf[2*p][1] = r4[1];
                    bhf[2*p+1][0] = r4[2]; bhf[2*p+1][1] = r4[3];
                    LDSM4(r4, b_base + KLOFF + p * 16 * 144 + ko);
                    blf[2*p][0] = r4[0]; blf[2*p][1] = r4[1];
                    blf[2*p+1][0] = r4[2]; blf[2*p+1][1] = r4[3];
                }
#pragma unroll
                for (int mt = 0; mt < 2; ++mt)
#pragma unroll
                    for (int nt = 0; nt < 4; ++nt) {
                        mma_bf16(acc[mt][nt], ah[mt], bhf[nt]);
                        mma_bf16(acc[mt][nt], ah[mt], blf[nt]);
                        mma_bf16(acc[mt][nt], al[mt], bhf[nt]);
                    }
            }
            if (c != 0) {
                const int s = c - 1;
                const float abs_s = ab[s];
                const size_t mrowbase = ((size_t)(s*BB + b) * LL + i0 + wm) * 16;
#pragma unroll
                for (int mt = 0; mt < 2; ++mt) {
                    const int rloc = mt * 16 + (lane >> 2);
                    unsigned mw0 = g_MB[mrowbase + (size_t)rloc * 16 + widx];
                    unsigned mw1 = g_MB[mrowbase + (size_t)(rloc + 8) * 16 + widx];
#pragma unroll
                    for (int nt = 0; nt < 4; ++nt) {
                        const int bp = nt * 8 + (lane & 3) * 2;
                        S[mt][nt][0] += (float)((mw0 >> bp) & 1u)     * (Sc[mt][nt][0] + abs_s);
                        S[mt][nt][1] += (float)((mw0 >> (bp+1)) & 1u) * (Sc[mt][nt][1] + abs_s);
                        S[mt][nt][2] += (float)((mw1 >> bp) & 1u)     * (Sc[mt][nt][2] + abs_s);
                        S[mt][nt][3] += (float)((mw1 >> (bp+1)) & 1u) * (Sc[mt][nt][3] + abs_s);
                    }
                }
            }
        }

        // ---- spill S fragments to sc ----
#pragma unroll
        for (int mt = 0; mt < 2; ++mt) {
            const int rr = wm + mt * 16 + (lane >> 2);
#pragma unroll
            for (int nt = 0; nt < 4; ++nt) {
                const int cc = wn + nt * 8 + (lane & 3) * 2;
                *(float2*)&sc[rr * 132 + cc]       = make_float2(S[mt][nt][0], S[mt][nt][1]);
                *(float2*)&sc[(rr + 8) * 132 + cc] = make_float2(S[mt][nt][2], S[mt][nt][3]);
            }
        }
        __syncthreads();

        // ---- online softmax (warp owns rows row0..row0+8), probs in place ----
        float amv[4];
#pragma unroll
        for (int jj = 0; jj < 4; ++jj)
            amv[jj] = __ldg(amask + (size_t)b * LL + j0 + lane + 32*jj);

#pragma unroll
        for (int ii = 0; ii < 8; ++ii) {
            const int r = row0 + ii;
            float lg[4];
            float mt = -1e30f;
#pragma unroll
            for (int jj = 0; jj < 4; ++jj) {
                lg[jj] = sc[r * 132 + lane + 32*jj] * 0.125f + amv[jj];
                mt = fmaxf(mt, lg[jj]);
            }
            mt = warp_max(mt);
            float mnew = fmaxf(mrow[ii], mt);
            float corr = __expf(mrow[ii] - mnew);
            mrow[ii] = mnew;
            float psum = 0.f;
#pragma unroll
            for (int jj = 0; jj < 4; ++jj) {
                float p = __expf(lg[jj] - mnew);
                sc[r * 132 + lane + 32*jj] = p;
                psum += p;
            }
            psum = warp_sum(psum);
            lrow[ii] = lrow[ii] * corr + psum;
            ull c2 = pack2(corr, corr);
            mul2(ctx2[ii][0], c2);
            mul2(ctx2[ii][1], c2);
        }
        __syncwarp();

        // ---- PV (FFMA2): own rows from sc, vt [d][j] ----
        const float* vr0 = &vt[lane * 130];
        const float* vr1 = &vt[(lane + 32) * 130];
#pragma unroll 2
        for (int j2 = 0; j2 < 64; ++j2) {
            ull vv0 = *(const ull*)(vr0 + 2*j2);
            ull vv1 = *(const ull*)(vr1 + 2*j2);
#pragma unroll
            for (int ii = 0; ii < 8; ++ii) {
                ull pp = *(const ull*)&sc[(row0 + ii) * 132 + 2*j2];
                fma2(ctx2[ii][0], pp, vv0);
                fma2(ctx2[ii][1], pp, vv1);
            }
        }
    }

    // ---- finalize ----
#pragma unroll
    for (int ii = 0; ii < 8; ++ii) {
        const int ig = i0 + row0 + ii;
        float inv = 1.f / lrow[ii];
        float* op = out + (size_t)(b * LL + ig) * (HH*DD) + h * DD;
        float2 c0 = unpack2(ctx2[ii][0]);
        float2 c1 = unpack2(ctx2[ii][1]);
        op[lane]      = (c0.x + c0.y) * inv;
        op[lane + 32] = (c1.x + c1.y) * inv;
    }
}

// =============================================================================
extern "C" void kernel_launch(void* const* d_in, const int* in_sizes, int n_in,
                              void* d_out, int out_size)
{
    const float* hs   = (const float*)d_in[0];
    const float* am   = (const float*)d_in[1];
    const float* smk  = (const float*)d_in[2];
    const float* Wq   = (const float*)d_in[3];
    const float* bq   = (const float*)d_in[4];
    const float* Wk   = (const float*)d_in[5];
    const float* bk   = (const float*)d_in[6];
    const float* Wv   = (const float*)d_in[7];
    const float* bv   = (const float*)d_in[8];
    const float* bili = (const float*)d_in[9];
    const float* absb = (const float*)d_in[10];
    float* out = (float*)d_out;

    pack_mask<<<(NSTRUCT*BB*LL*LL)/256, 256>>>(smk);
    cvt_hs<<<(BB*LL*HIDN/4)/256, 256>>>(hs);
    cvt_w<<<(3*HIDN*HIDN/4)/256, 256>>>(Wq, Wk, Wv);

    cudaFuncSetAttribute(qkv_mma_kernel, cudaFuncAttributeMaxDynamicSharedMemorySize, QT_SMEM);
    qkv_mma_kernel<<<dim3(64, 6, 3), 256, QT_SMEM>>>(bq, bk, bv);

    qb_kernel<<<dim3(128, 12, 5), 256>>>(bili);

    cudaFuncSetAttribute(attn_kernel, cudaFuncAttributeMaxDynamicSharedMemorySize, A_TOT);
    attn_kernel<<<dim3(8, 192), 256, A_TOT>>>(am, absb, out);
}